// round 16
// baseline (speedup 1.0000x reference)
#include <cuda_runtime.h>
#include <cuda_fp16.h>
#include <cstdint>

#define NV   100000
#define MPAD 100096          // 782 * 128
#define NG   64
#define HIDN 256
#define EMAX 3211264

// ---------------- scratch (device globals; no allocation allowed) ----------------
__device__ float  d_norm[NV];    // deg^-1/2
__device__ float  d_invn[NV];    // deg^+1/2
__device__ int    d_cnt[NV];     // zero at launch entry (.bss first call, tail-zero after)
__device__ int    d_rowptr[NV + 1];
__device__ int    d_blktot[128];
__device__ int    d_blkoff[128];
__device__ int    d_eslot[EMAX]; // per-edge within-node slot (from degi's atomic return)
__device__ int    d_esrc[EMAX];
// All slot buffers store values PRE-SCALED by norm[v]; pad rows stay .bss zero.
__device__ __half d_h16 [(size_t)MPAD * 128];   // GEMM1 slot0 = h*n, hop-0 gather src
__device__ __half d_hop1[(size_t)MPAD * 128];   // GEMM1 slot1 = cur1*n, hop-1 gather src
__device__ __half d_hop2[(size_t)MPAD * 128];   // GEMM1 slot2 = cur2*n (final hop)
__device__ __half d_x1h [(size_t)MPAD * 256];   // GEMM2 slot0 = x1*n, layer2 gather src
__device__ __half d_g1  [(size_t)MPAD * 256];   // GEMM2 slot1 (gather src for hop2)
__device__ __half d_g2  [(size_t)MPAD * 256];   // GEMM2 slot2 (final hop)
__device__ __half d_w1h[384 * 256];
__device__ __half d_w2h[768 * 256];
__device__ float  d_pooled[NG * HIDN];          // zero at entry (same invariant as cnt)

// ---------------- utility kernels ----------------
__global__ void k_zero(float4* __restrict__ p, long n4) {
    long i = (long)blockIdx.x * blockDim.x + threadIdx.x;
    if (i < n4) p[i] = make_float4(0.f, 0.f, 0.f, 0.f);
}

// degree count; atomic return value IS the edge's CSR slot — store it
__global__ void k_degi(const int* __restrict__ dst, int E) {
    int i = blockIdx.x * blockDim.x + threadIdx.x;
    if (i < E) d_eslot[i] = atomicAdd(&d_cnt[dst[i]], 1);
}

// ---------------- prefix scan (1024 elems / block) ----------------
__global__ __launch_bounds__(256) void k_scan_local() {
    __shared__ int sh[256];
    int b = blockIdx.x, t = threadIdx.x;
    int base = b * 1024 + t * 4;
    int c[4];
#pragma unroll
    for (int i = 0; i < 4; i++) c[i] = (base + i < NV) ? d_cnt[base + i] : 0;
    int sum = c[0] + c[1] + c[2] + c[3];
    sh[t] = sum;
    __syncthreads();
    for (int off = 1; off < 256; off <<= 1) {
        int x = (t >= off) ? sh[t - off] : 0;
        __syncthreads();
        sh[t] += x;
        __syncthreads();
    }
    int run = sh[t] - sum;
#pragma unroll
    for (int i = 0; i < 4; i++) {
        if (base + i < NV) d_rowptr[base + i] = run;
        run += c[i];
    }
    if (t == 255) d_blktot[b] = sh[255];
}

// parallel scan over block totals (one 128-thread block)
__global__ void k_scan_blk(int nb) {
    __shared__ int sh[128];
    int t = threadIdx.x;
    int v = (t < nb) ? d_blktot[t] : 0;
    sh[t] = v;
    __syncthreads();
    for (int off = 1; off < 128; off <<= 1) {
        int x = (t >= off) ? sh[t - off] : 0;
        __syncthreads();
        sh[t] += x;
        __syncthreads();
    }
    if (t < nb) d_blkoff[t] = sh[t] - v;
}

// also computes norm/invn from cnt (fused)
__global__ void k_addoff(int E) {
    int i = blockIdx.x * blockDim.x + threadIdx.x;
    if (i < NV) {
        d_rowptr[i] = d_rowptr[i] + d_blkoff[i >> 10];
        float dg = fmaxf((float)d_cnt[i], 1.0f);
        d_norm[i] = rsqrtf(dg);
        d_invn[i] = sqrtf(dg);
    }
    if (i == 0) d_rowptr[NV] = E;
}

// atomic-free CSR fill: slot precomputed by k_degi
__global__ void k_csrbuild(const int* __restrict__ src, const int* __restrict__ dst, int E) {
    int e = blockIdx.x * blockDim.x + threadIdx.x;
    if (e < E)
        d_esrc[__ldg(&d_rowptr[dst[e]]) + d_eslot[e]] = src[e];
}

// fp32 -> fp16 weight conversion
__global__ void k_roundh(__half* __restrict__ o, const float* __restrict__ in, int n2) {
    int i = blockIdx.x * blockDim.x + threadIdx.x;
    if (i < n2) {
        float2 v = ((const float2*)in)[i];
        ((__half2*)o)[i] = __floats2half2_rn(v.x, v.y);
    }
}

__device__ __forceinline__ uint4 pack8h(const float* f) {
    __half2 h0 = __floats2half2_rn(f[0], f[1]);
    __half2 h1 = __floats2half2_rn(f[2], f[3]);
    __half2 h2 = __floats2half2_rn(f[4], f[5]);
    __half2 h3 = __floats2half2_rn(f[6], f[7]);
    uint4 u;
    u.x = *(uint32_t*)&h0; u.y = *(uint32_t*)&h1;
    u.z = *(uint32_t*)&h2; u.w = *(uint32_t*)&h3;
    return u;
}

// prep0: h16 = fp16(h * norm)
__global__ void k_prep0(const float4* __restrict__ in, uint4* __restrict__ h16) {
    long idx = (long)blockIdx.x * blockDim.x + threadIdx.x;
    if (idx >= (long)NV * 16) return;
    int i = (int)(idx >> 4);
    float n = d_norm[i];
    float4 v0 = in[idx * 2], v1 = in[idx * 2 + 1];
    float f[8] = {v0.x * n, v0.y * n, v0.z * n, v0.w * n,
                  v1.x * n, v1.y * n, v1.z * n, v1.w * n};
    h16[idx] = pack8h(f);
}

// ---------------- CSR aggregation (index loads software-pipelined) ----------------
// Source buf is pre-scaled by norm[u]; single load stream (no per-edge norm).
// hop[v] = fp16( (sum_e buf[esrc[e]]) * norm[v]^2 ) == cur_{k+1}[v] * norm[v]
// STREAM=true (final hop only, consumed linearly by GEMM): evict-first stores so
// the current gather source stays L2-resident. NEVER stream a future gather src (R8!).
template <int D, bool STREAM>
__global__ __launch_bounds__(256) void k_agg(const __half* __restrict__ buf,
                                             __half* __restrict__ hop) {
    const int LPE = D / 8;
    const int gpb = 256 / LPE;
    int v = blockIdx.x * gpb + threadIdx.x / LPE;
    int lane = threadIdx.x % LPE;
    if (v >= NV) return;
    int beg = __ldg(&d_rowptr[v]);
    int end = __ldg(&d_rowptr[v + 1]);
    float a0[8], a1[8], a2[8], a3[8];
#pragma unroll
    for (int i = 0; i < 8; i++) { a0[i] = 0.f; a1[i] = 0.f; a2[i] = 0.f; a3[i] = 0.f; }

    auto accum = [&](float* a, int node) {
        const uint4 u = __ldg((const uint4*)(buf + (size_t)node * D) + lane);
        float2 f0 = __half22float2(*(const __half2*)&u.x);
        float2 f1 = __half22float2(*(const __half2*)&u.y);
        float2 f2 = __half22float2(*(const __half2*)&u.z);
        float2 f3 = __half22float2(*(const __half2*)&u.w);
        a[0] += f0.x; a[1] += f0.y; a[2] += f1.x; a[3] += f1.y;
        a[4] += f2.x; a[5] += f2.y; a[6] += f3.x; a[7] += f3.y;
    };

    // software pipeline: prefetch next 4 indices while gathering/accumulating current 4
    int e = beg;
    int s0, s1, s2, s3;
    bool have = (e + 3 < end);
    if (have) {
        s0 = __ldg(&d_esrc[e]);
        s1 = __ldg(&d_esrc[e + 1]);
        s2 = __ldg(&d_esrc[e + 2]);
        s3 = __ldg(&d_esrc[e + 3]);
    }
    while (have) {
        int c0 = s0, c1 = s1, c2 = s2, c3 = s3;
        e += 4;
        have = (e + 3 < end);
        if (have) {
            s0 = __ldg(&d_esrc[e]);
            s1 = __ldg(&d_esrc[e + 1]);
            s2 = __ldg(&d_esrc[e + 2]);
            s3 = __ldg(&d_esrc[e + 3]);
        }
        accum(a0, c0); accum(a1, c1); accum(a2, c2); accum(a3, c3);
    }
    for (; e < end; e++) accum(a0, __ldg(&d_esrc[e]));

    float n = __ldg(&d_norm[v]);
    float m2 = n * n;
    float cur[8];
#pragma unroll
    for (int i = 0; i < 8; i++)
        cur[i] = ((a0[i] + a1[i]) + (a2[i] + a3[i])) * m2;

    uint4 uh = pack8h(cur);
    if (STREAM)
        __stcs((float4*)((uint4*)(hop + (size_t)v * D) + lane), *(float4*)&uh);
    else
        ((uint4*)(hop + (size_t)v * D))[lane] = uh;
}

// ---------------- fp16 tensor-core GEMM (ldmatrix + m16n8k16, 3-stage) ----------------
// A rows are pre-scaled by norm[row]; epilogue multiplies acc by invn[row].
#define BM 128
#define BN 128
#define BKH 64                   // k-halves per tile (128 bytes)
#define A_BYTES (BM * 128)       // 16384
#define B_BYTES (BKH * 256)      // 16384
#define STAGE_BYTES (A_BYTES + B_BYTES)
#define NSTAGE 3
#define GEMM_SMEM_BYTES (NSTAGE * STAGE_BYTES)
#define POOL_STRIDE 132

extern __shared__ char smem_gemm[];

__device__ __forceinline__ void cp16(uint32_t s, const void* g) {
    asm volatile("cp.async.cg.shared.global [%0], [%1], 16;\n" :: "r"(s), "l"(g));
}
__device__ __forceinline__ void cp_commit() { asm volatile("cp.async.commit_group;\n"); }
template <int N>
__device__ __forceinline__ void cp_wait() { asm volatile("cp.async.wait_group %0;\n" :: "n"(N)); }

__device__ __forceinline__ void ldsm4(uint32_t* r, uint32_t a) {
    asm volatile("ldmatrix.sync.aligned.m8n8.x4.shared.b16 {%0,%1,%2,%3}, [%4];"
                 : "=r"(r[0]), "=r"(r[1]), "=r"(r[2]), "=r"(r[3]) : "r"(a));
}
__device__ __forceinline__ void ldsm2t(uint32_t* r, uint32_t a) {
    asm volatile("ldmatrix.sync.aligned.m8n8.x2.trans.shared.b16 {%0,%1}, [%2];"
                 : "=r"(r[0]), "=r"(r[1]) : "r"(a));
}

__device__ __forceinline__ void mma_f16(float* c, const uint32_t* a, const uint32_t* b) {
    asm volatile(
        "mma.sync.aligned.m16n8k16.row.col.f32.f16.f16.f32 "
        "{%0,%1,%2,%3}, {%4,%5,%6,%7}, {%8,%9}, {%0,%1,%2,%3};"
        : "+f"(c[0]), "+f"(c[1]), "+f"(c[2]), "+f"(c[3])
        : "r"(a[0]), "r"(a[1]), "r"(a[2]), "r"(a[3]), "r"(b[0]), "r"(b[1]));
}

// EPI=0: fused segment-max pooling into d_pooled (gidp = sorted graph ids)
// EPI=1: xOut(fp16)[row*256+col] = relu(acc*invn+bias) * norm   (pad rows -> 0)
template <int EPI, int SWS>
__global__ __launch_bounds__(256) void k_gemm_f16(const __half* __restrict__ S0,
                                                  const __half* __restrict__ S1,
                                                  const __half* __restrict__ S2,
                                                  const __half* __restrict__ Bh,
                                                  const float* __restrict__ bias,
                                                  const int* __restrict__ gidp, int Kdim,
                                                  __half* __restrict__ xOut) {
    const int SW = 1 << SWS;
    const int tid  = threadIdx.x;
    const int lane = tid & 31, warp = tid >> 5;
    const int gid  = lane >> 2, qid = lane & 3;
    const int wm   = (warp & 1) * 64;
    const int wn   = (warp >> 1) * 32;
    const long mbase = (long)blockIdx.y * BM;
    const int  nbase = blockIdx.x * BN;

    float acc[4][4][4];
#pragma unroll
    for (int mi = 0; mi < 4; mi++)
#pragma unroll
        for (int ni = 0; ni < 4; ni++)
#pragma unroll
            for (int r = 0; r < 4; r++) acc[mi][ni][r] = 0.f;

    const uint32_t smemB = (uint32_t)__cvta_generic_to_shared(smem_gemm);
    const int ntiles = Kdim / BKH;

    auto load_stage = [&](int t, int buf) {
        uint32_t sb = smemB + buf * STAGE_BYTES;
#pragma unroll
        for (int i = 0; i < 4; i++) {
            int ch = tid + 256 * i;
            int r = ch >> 3, kc = ch & 7;
            uint32_t dstA = sb + r * 128 + ((kc * 16) ^ ((r & 7) * 16));
            int kh = t * BKH + kc * 8;
            int sl = kh >> SWS;
            int off = kh & (SW - 1);
            const __half* base = (sl == 0) ? S0 : ((sl == 1) ? S1 : S2);
            cp16(dstA, base + (size_t)(mbase + r) * SW + off);
        }
#pragma unroll
        for (int i = 0; i < 4; i++) {
            int ch = tid + 256 * i;
            int r = ch >> 4, nc = ch & 15;
            uint32_t dstB = sb + A_BYTES + r * 256 + ((nc * 16) ^ ((r & 7) * 16));
            cp16(dstB, Bh + (size_t)(t * BKH + r) * 256 + nbase + nc * 8);
        }
        cp_commit();
    };

    const int Lr = lane & 7, sub = lane >> 3;
    const int rowLocal = Lr + (sub & 1) * 8;
    const int ksub16 = (sub >> 1) * 16;
    const uint32_t xorA = Lr * 16;
    const int bl = lane & 15;
    const uint32_t xorB = (lane & 7) * 16;

    load_stage(0, 0);
    load_stage(1, 1);
    for (int t = 0; t < ntiles; t++) {
        if (t + 2 < ntiles) { load_stage(t + 2, (t + 2) % NSTAGE); cp_wait<2>(); }
        else if (t + 1 < ntiles) cp_wait<1>();
        else cp_wait<0>();
        __syncthreads();
        uint32_t As = smemB + (t % NSTAGE) * STAGE_BYTES;
        uint32_t Bs = As + A_BYTES;
        uint32_t aRow[4];
#pragma unroll
        for (int mi = 0; mi < 4; mi++)
            aRow[mi] = As + (wm + mi * 16 + rowLocal) * 128;
        uint32_t bBase = Bs + bl * 256;
        uint32_t bOff[4];
#pragma unroll
        for (int ni = 0; ni < 4; ni++)
            bOff[ni] = (uint32_t)((wn + ni * 8) * 2) ^ xorB;
#pragma unroll
        for (int ks = 0; ks < 4; ks++) {
            uint32_t a[4][4], b[4][2];
#pragma unroll
            for (int mi = 0; mi < 4; mi++)
                ldsm4(a[mi], aRow[mi] + (uint32_t)((ks * 32 + ksub16) ^ xorA));
#pragma unroll
            for (int ni = 0; ni < 4; ni++)
                ldsm2t(b[ni], bBase + ks * 4096 + bOff[ni]);
#pragma unroll
            for (int mi = 0; mi < 4; mi++)
#pragma unroll
                for (int ni = 0; ni < 4; ni++)
                    mma_f16(acc[mi][ni], a[mi], b[ni]);
        }
        __syncthreads();
    }

    if (EPI == 1) {
#pragma unroll
        for (int mi = 0; mi < 4; mi++) {
            long r0 = mbase + wm + mi * 16 + gid;
            long r1 = r0 + 8;
            float i0 = (r0 < NV) ? __ldg(&d_invn[r0]) : 0.f;
            float i1 = (r1 < NV) ? __ldg(&d_invn[r1]) : 0.f;
            float n0 = (r0 < NV) ? __ldg(&d_norm[r0]) : 0.f;
            float n1 = (r1 < NV) ? __ldg(&d_norm[r1]) : 0.f;
#pragma unroll
            for (int ni = 0; ni < 4; ni++) {
                int col = nbase + wn + ni * 8 + 2 * qid;
                float b0 = bias[col], b1v = bias[col + 1];
                float v00 = fmaxf(fmaf(acc[mi][ni][0], i0, b0), 0.f);
                float v01 = fmaxf(fmaf(acc[mi][ni][1], i0, b1v), 0.f);
                float v10 = fmaxf(fmaf(acc[mi][ni][2], i1, b0), 0.f);
                float v11 = fmaxf(fmaf(acc[mi][ni][3], i1, b1v), 0.f);
                *(__half2*)&xOut[r0 * 256 + col] = __floats2half2_rn(v00 * n0, v01 * n0);
                *(__half2*)&xOut[r1 * 256 + col] = __floats2half2_rn(v10 * n1, v11 * n1);
            }
        }
    } else {
        // ---- fused segment-max pooling (all 256 threads: 2 row-halves per column) ----
        float* pool = (float*)smem_gemm;                         // [128][POOL_STRIDE]
        int* gsh = (int*)(smem_gemm + 128 * POOL_STRIDE * 4);    // [128]
#pragma unroll
        for (int mi = 0; mi < 4; mi++) {
            int rr0 = wm + mi * 16 + gid;
            int rr1 = rr0 + 8;
            long r0 = mbase + rr0, r1 = mbase + rr1;
            float i0 = (r0 < NV) ? __ldg(&d_invn[r0]) : 0.f;
            float i1 = (r1 < NV) ? __ldg(&d_invn[r1]) : 0.f;
#pragma unroll
            for (int ni = 0; ni < 4; ni++) {
                int c = wn + ni * 8 + 2 * qid;
                float b0 = bias[nbase + c], b1v = bias[nbase + c + 1];
                pool[rr0 * POOL_STRIDE + c]     = fmaxf(fmaf(acc[mi][ni][0], i0, b0), 0.f);
                pool[rr0 * POOL_STRIDE + c + 1] = fmaxf(fmaf(acc[mi][ni][1], i0, b1v), 0.f);
                pool[rr1 * POOL_STRIDE + c]     = fmaxf(fmaf(acc[mi][ni][2], i1, b0), 0.f);
                pool[rr1 * POOL_STRIDE + c + 1] = fmaxf(fmaf(acc[mi][ni][3], i1, b1v), 0.f);
            }
        }
        if (tid < 128) {
            long r = mbase + tid;
            gsh[tid] = (r < NV) ? __ldg(&gidp[r]) : -1;
        }
        __syncthreads();
        {
            int col  = tid & 127;
            int rlo  = (tid >> 7) * 64;        // 0 or 64
            int rhi  = rlo + 64;
            int g = gsh[rlo];
            float m = 0.f;
            for (int r = rlo; r < rhi; r++) {
                int g2 = gsh[r];
                if (g2 < 0) break;
                if (g2 != g) {
                    atomicMax((int*)&d_pooled[g * HIDN + nbase + col], __float_as_int(m));
                    m = 0.f;
                    g = g2;
                }
                m = fmaxf(m, pool[r * POOL_STRIDE + col]);
            }
            if (g >= 0)
                atomicMax((int*)&d_pooled[g * HIDN + nbase + col], __float_as_int(m));
        }
    }
}

// head + fused pooled tail-zero: 2 blocks x 320 threads, block b owns graphs
// [b*32, b*32+32) exclusively (reads AND zeroes only its own rows -> no race).
__global__ __launch_bounds__(320) void k_head(const float* __restrict__ Wc,
                                              const float* __restrict__ bc,
                                              float* __restrict__ out) {
    int b = blockIdx.x, t = threadIdx.x;
    int g = b * 32 + t / 10, c = t % 10;
    if (t < 320) {
        float s = bc[c];
#pragma unroll 8
        for (int hh = 0; hh < HIDN; hh++)
            s = fmaf(d_pooled[g * HIDN + hh], Wc[hh * 10 + c], s);
        out[g * 10 + c] = s;
    }
    __syncthreads();
    // zero this block's 32 pooled rows (32*256 floats = 2048 float4)
    float4* pz = (float4*)&d_pooled[b * 32 * HIDN];
    for (int i = t; i < 32 * HIDN / 4; i += 320)
        pz[i] = make_float4(0.f, 0.f, 0.f, 0.f);
}

// ---------------- launch ----------------
extern "C" void kernel_launch(void* const* d_in, const int* in_sizes, int n_in,
                              void* d_out, int out_size) {
    const float* h   = (const float*)d_in[0];
    const int*   src = (const int*)d_in[1];
    const int*   dst = (const int*)d_in[2];
    const int*   gid = (const int*)d_in[3];
    const float* W1  = (const float*)d_in[4];
    const float* b1  = (const float*)d_in[5];
    const float* W2  = (const float*)d_in[6];
    const float* b2  = (const float*)d_in[7];
    const float* Wc  = (const float*)d_in[8];
    const float* bc  = (const float*)d_in[9];
    float* out = (float*)d_out;
    const int E = in_sizes[1];

    __half *h16_, *hop1_, *hop2_, *x1h_, *g1_, *g2_, *w1h_, *w2h_;
    int *cnt_;
    cudaGetSymbolAddress((void**)&h16_,  d_h16);
    cudaGetSymbolAddress((void**)&hop1_, d_hop1);
    cudaGetSymbolAddress((void**)&hop2_, d_hop2);
    cudaGetSymbolAddress((void**)&x1h_,  d_x1h);
    cudaGetSymbolAddress((void**)&g1_,   d_g1);
    cudaGetSymbolAddress((void**)&g2_,   d_g2);
    cudaGetSymbolAddress((void**)&w1h_,  d_w1h);
    cudaGetSymbolAddress((void**)&w2h_,  d_w2h);
    cudaGetSymbolAddress((void**)&cnt_,  d_cnt);

    cudaFuncSetAttribute((const void*)k_gemm_f16<1, 7>,
                         cudaFuncAttributeMaxDynamicSharedMemorySize, GEMM_SMEM_BYTES);
    cudaFuncSetAttribute((const void*)k_gemm_f16<0, 8>,
                         cudaFuncAttributeMaxDynamicSharedMemorySize, GEMM_SMEM_BYTES);

    static cudaStream_t s1 = nullptr;
    static cudaEvent_t evFork = nullptr, evNorm = nullptr, evJoin = nullptr;
    if (!s1) {
        cudaStreamCreateWithFlags(&s1, cudaStreamNonBlocking);
        cudaEventCreateWithFlags(&evFork, cudaEventDisableTiming);
        cudaEventCreateWithFlags(&evNorm, cudaEventDisableTiming);
        cudaEventCreateWithFlags(&evJoin, cudaEventDisableTiming);
    }

    // ---- fork: weights on s1 (independent); degree chain on main ----
    // Invariant: d_cnt and d_pooled are ZERO at launch entry (.bss on first call;
    // tail-zeroed inside every launch thereafter -> holds for each graph replay).
    cudaEventRecord(evFork, 0);
    cudaStreamWaitEvent(s1, evFork, 0);
    k_roundh<<<(384 * 128 + 255) / 256, 256, 0, s1>>>(w1h_, W1, 384 * 128);
    k_roundh<<<(768 * 128 + 255) / 256, 256, 0, s1>>>(w2h_, W2, 768 * 128);

    k_degi<<<(E + 255) / 256, 256>>>(dst, E);
    const int NB = (NV + 1023) / 1024;
    k_scan_local<<<NB, 256>>>();
    k_scan_blk<<<1, 128>>>(NB);
    k_addoff<<<(NV + 255) / 256, 256>>>(E);
    cudaEventRecord(evNorm, 0);

    // csrbuild (atomic-free) on main; prep0 + cnt tail-zero on s1
    cudaStreamWaitEvent(s1, evNorm, 0);
    k_prep0<<<(unsigned)(((long)NV * 16 + 255) / 256), 256, 0, s1>>>((const float4*)h,
                                                                     (uint4*)h16_);
    k_zero<<<(NV / 4 + 255) / 256, 256, 0, s1>>>((float4*)cnt_, NV / 4);
    cudaEventRecord(evJoin, s1);
    k_csrbuild<<<(E + 255) / 256, 256>>>(src, dst, E);
    cudaStreamWaitEvent(0, evJoin, 0);

    // ---- layer 1 (d=128) ----
    k_agg<128, false><<<(NV + 15) / 16, 256>>>(h16_, hop1_);
    k_agg<128, true ><<<(NV + 15) / 16, 256>>>(hop1_, hop2_);   // final hop: stream
    k_gemm_f16<1, 7><<<dim3(2, MPAD / 128), 256, GEMM_SMEM_BYTES>>>(
        h16_, hop1_, hop2_, w1h_, b1, nullptr, 384, x1h_);

    // ---- layer 2 (d=256) ----
    k_agg<256, false><<<(NV + 7) / 8, 256>>>(x1h_, g1_);
    k_agg<256, true ><<<(NV + 7) / 8, 256>>>(g1_, g2_);         // final hop: stream
    k_gemm_f16<0, 8><<<dim3(2, MPAD / 128), 256, GEMM_SMEM_BYTES>>>(
        x1h_, g1_, g2_, w2h_, b2, gid, 768, nullptr);

    // ---- head (fused pooled tail-zero) ----
    k_head<<<2, 320>>>(Wc, bc, out);
}

// round 17
// speedup vs baseline: 1.0544x; 1.0544x over previous
#include <cuda_runtime.h>
#include <cuda_fp16.h>
#include <cstdint>

#define NV   100000
#define MPAD 100096          // 782 * 128
#define NG   64
#define HIDN 256
#define EMAX 3211264

// ---------------- scratch (device globals; no allocation allowed) ----------------
__device__ float  d_norm[NV];    // deg^-1/2
__device__ float  d_invn[NV];    // deg^+1/2
__device__ int    d_cnt[NV];     // zero at launch entry (.bss first call, tail-zero after)
__device__ int    d_rowptr[NV + 1];
__device__ int    d_blktot[128];
__device__ int    d_blkoff[128];
__device__ int    d_eslot[EMAX]; // per-edge within-node slot (from degi's atomic return)
__device__ int    d_esrc[EMAX];
// All slot buffers store values PRE-SCALED by norm[v]; pad rows stay .bss zero.
__device__ __half d_h16 [(size_t)MPAD * 128];   // GEMM1 slot0 = h*n, hop-0 gather src
__device__ __half d_hop1[(size_t)MPAD * 128];   // GEMM1 slot1 = cur1*n, hop-1 gather src
__device__ __half d_hop2[(size_t)MPAD * 128];   // GEMM1 slot2 = cur2*n (final hop)
__device__ __half d_x1h [(size_t)MPAD * 256];   // GEMM2 slot0 = x1*n, layer2 gather src
__device__ __half d_g1  [(size_t)MPAD * 256];   // GEMM2 slot1 (gather src for hop2)
__device__ __half d_g2  [(size_t)MPAD * 256];   // GEMM2 slot2 (final hop)
__device__ __half d_w1h[384 * 256];
__device__ __half d_w2h[768 * 256];
__device__ float  d_pooled[NG * HIDN];          // zero at entry (same invariant as cnt)

// ---------------- utility kernels ----------------
__global__ void k_zero(float4* __restrict__ p, long n4) {
    long i = (long)blockIdx.x * blockDim.x + threadIdx.x;
    if (i < n4) p[i] = make_float4(0.f, 0.f, 0.f, 0.f);
}

// degree count; atomic return value IS the edge's CSR slot — store it
__global__ void k_degi(const int* __restrict__ dst, int E) {
    int i = blockIdx.x * blockDim.x + threadIdx.x;
    if (i < E) d_eslot[i] = atomicAdd(&d_cnt[dst[i]], 1);
}

// ---------------- prefix scan (1024 elems / block) ----------------
__global__ __launch_bounds__(256) void k_scan_local() {
    __shared__ int sh[256];
    int b = blockIdx.x, t = threadIdx.x;
    int base = b * 1024 + t * 4;
    int c[4];
#pragma unroll
    for (int i = 0; i < 4; i++) c[i] = (base + i < NV) ? d_cnt[base + i] : 0;
    int sum = c[0] + c[1] + c[2] + c[3];
    sh[t] = sum;
    __syncthreads();
    for (int off = 1; off < 256; off <<= 1) {
        int x = (t >= off) ? sh[t - off] : 0;
        __syncthreads();
        sh[t] += x;
        __syncthreads();
    }
    int run = sh[t] - sum;
#pragma unroll
    for (int i = 0; i < 4; i++) {
        if (base + i < NV) d_rowptr[base + i] = run;
        run += c[i];
    }
    if (t == 255) d_blktot[b] = sh[255];
}

// parallel scan over block totals (one 128-thread block)
__global__ void k_scan_blk(int nb) {
    __shared__ int sh[128];
    int t = threadIdx.x;
    int v = (t < nb) ? d_blktot[t] : 0;
    sh[t] = v;
    __syncthreads();
    for (int off = 1; off < 128; off <<= 1) {
        int x = (t >= off) ? sh[t - off] : 0;
        __syncthreads();
        sh[t] += x;
        __syncthreads();
    }
    if (t < nb) d_blkoff[t] = sh[t] - v;
}

// also computes norm/invn from cnt (fused)
__global__ void k_addoff(int E) {
    int i = blockIdx.x * blockDim.x + threadIdx.x;
    if (i < NV) {
        d_rowptr[i] = d_rowptr[i] + d_blkoff[i >> 10];
        float dg = fmaxf((float)d_cnt[i], 1.0f);
        d_norm[i] = rsqrtf(dg);
        d_invn[i] = sqrtf(dg);
    }
    if (i == 0) d_rowptr[NV] = E;
}

// atomic-free CSR fill: slot precomputed by k_degi
__global__ void k_csrbuild(const int* __restrict__ src, const int* __restrict__ dst, int E) {
    int e = blockIdx.x * blockDim.x + threadIdx.x;
    if (e < E)
        d_esrc[__ldg(&d_rowptr[dst[e]]) + d_eslot[e]] = src[e];
}

// fp32 -> fp16 weight conversion
__global__ void k_roundh(__half* __restrict__ o, const float* __restrict__ in, int n2) {
    int i = blockIdx.x * blockDim.x + threadIdx.x;
    if (i < n2) {
        float2 v = ((const float2*)in)[i];
        ((__half2*)o)[i] = __floats2half2_rn(v.x, v.y);
    }
}

__device__ __forceinline__ uint4 pack8h(const float* f) {
    __half2 h0 = __floats2half2_rn(f[0], f[1]);
    __half2 h1 = __floats2half2_rn(f[2], f[3]);
    __half2 h2 = __floats2half2_rn(f[4], f[5]);
    __half2 h3 = __floats2half2_rn(f[6], f[7]);
    uint4 u;
    u.x = *(uint32_t*)&h0; u.y = *(uint32_t*)&h1;
    u.z = *(uint32_t*)&h2; u.w = *(uint32_t*)&h3;
    return u;
}

// prep0: h16 = fp16(h * norm)
__global__ void k_prep0(const float4* __restrict__ in, uint4* __restrict__ h16) {
    long idx = (long)blockIdx.x * blockDim.x + threadIdx.x;
    if (idx >= (long)NV * 16) return;
    int i = (int)(idx >> 4);
    float n = d_norm[i];
    float4 v0 = in[idx * 2], v1 = in[idx * 2 + 1];
    float f[8] = {v0.x * n, v0.y * n, v0.z * n, v0.w * n,
                  v1.x * n, v1.y * n, v1.z * n, v1.w * n};
    h16[idx] = pack8h(f);
}

// ---------------- CSR aggregation (R15-validated straight-line loop) ----------------
// Source buf is pre-scaled by norm[u]; single load stream (no per-edge norm).
// hop[v] = fp16( (sum_e buf[esrc[e]]) * norm[v]^2 ) == cur_{k+1}[v] * norm[v]
// STREAM=true (final hop only, consumed linearly by GEMM): evict-first stores so
// the current gather source stays L2-resident. NEVER stream a future gather src (R8!).
template <int D, bool STREAM>
__global__ __launch_bounds__(256) void k_agg(const __half* __restrict__ buf,
                                             __half* __restrict__ hop) {
    const int LPE = D / 8;
    const int gpb = 256 / LPE;
    int v = blockIdx.x * gpb + threadIdx.x / LPE;
    int lane = threadIdx.x % LPE;
    if (v >= NV) return;
    int beg = __ldg(&d_rowptr[v]);
    int end = __ldg(&d_rowptr[v + 1]);
    float a0[8], a1[8], a2[8], a3[8];
#pragma unroll
    for (int i = 0; i < 8; i++) { a0[i] = 0.f; a1[i] = 0.f; a2[i] = 0.f; a3[i] = 0.f; }

    auto accum = [&](float* a, int node) {
        const uint4 u = __ldg((const uint4*)(buf + (size_t)node * D) + lane);
        float2 f0 = __half22float2(*(const __half2*)&u.x);
        float2 f1 = __half22float2(*(const __half2*)&u.y);
        float2 f2 = __half22float2(*(const __half2*)&u.z);
        float2 f3 = __half22float2(*(const __half2*)&u.w);
        a[0] += f0.x; a[1] += f0.y; a[2] += f1.x; a[3] += f1.y;
        a[4] += f2.x; a[5] += f2.y; a[6] += f3.x; a[7] += f3.y;
    };

    int e = beg;
    for (; e + 3 < end; e += 4) {
        int s0 = __ldg(&d_esrc[e]);
        int s1 = __ldg(&d_esrc[e + 1]);
        int s2 = __ldg(&d_esrc[e + 2]);
        int s3 = __ldg(&d_esrc[e + 3]);
        accum(a0, s0); accum(a1, s1); accum(a2, s2); accum(a3, s3);
    }
    for (; e < end; e++) accum(a0, __ldg(&d_esrc[e]));

    float n = __ldg(&d_norm[v]);
    float m2 = n * n;
    float cur[8];
#pragma unroll
    for (int i = 0; i < 8; i++)
        cur[i] = ((a0[i] + a1[i]) + (a2[i] + a3[i])) * m2;

    uint4 uh = pack8h(cur);
    if (STREAM)
        __stcs((float4*)((uint4*)(hop + (size_t)v * D) + lane), *(float4*)&uh);
    else
        ((uint4*)(hop + (size_t)v * D))[lane] = uh;
}

// ---------------- fp16 tensor-core GEMM (ldmatrix + m16n8k16, 3-stage) ----------------
// A rows are pre-scaled by norm[row]; epilogue multiplies acc by invn[row].
#define BM 128
#define BN 128
#define BKH 64                   // k-halves per tile (128 bytes)
#define A_BYTES (BM * 128)       // 16384
#define B_BYTES (BKH * 256)      // 16384
#define STAGE_BYTES (A_BYTES + B_BYTES)
#define NSTAGE 3
#define GEMM_SMEM_BYTES (NSTAGE * STAGE_BYTES)
#define POOL_STRIDE 132

extern __shared__ char smem_gemm[];

__device__ __forceinline__ void cp16(uint32_t s, const void* g) {
    asm volatile("cp.async.cg.shared.global [%0], [%1], 16;\n" :: "r"(s), "l"(g));
}
__device__ __forceinline__ void cp_commit() { asm volatile("cp.async.commit_group;\n"); }
template <int N>
__device__ __forceinline__ void cp_wait() { asm volatile("cp.async.wait_group %0;\n" :: "n"(N)); }

__device__ __forceinline__ void ldsm4(uint32_t* r, uint32_t a) {
    asm volatile("ldmatrix.sync.aligned.m8n8.x4.shared.b16 {%0,%1,%2,%3}, [%4];"
                 : "=r"(r[0]), "=r"(r[1]), "=r"(r[2]), "=r"(r[3]) : "r"(a));
}
__device__ __forceinline__ void ldsm2t(uint32_t* r, uint32_t a) {
    asm volatile("ldmatrix.sync.aligned.m8n8.x2.trans.shared.b16 {%0,%1}, [%2];"
                 : "=r"(r[0]), "=r"(r[1]) : "r"(a));
}

__device__ __forceinline__ void mma_f16(float* c, const uint32_t* a, const uint32_t* b) {
    asm volatile(
        "mma.sync.aligned.m16n8k16.row.col.f32.f16.f16.f32 "
        "{%0,%1,%2,%3}, {%4,%5,%6,%7}, {%8,%9}, {%0,%1,%2,%3};"
        : "+f"(c[0]), "+f"(c[1]), "+f"(c[2]), "+f"(c[3])
        : "r"(a[0]), "r"(a[1]), "r"(a[2]), "r"(a[3]), "r"(b[0]), "r"(b[1]));
}

// EPI=0: fused segment-max pooling into d_pooled (gidp = sorted graph ids)
// EPI=1: xOut(fp16)[row*256+col] = relu(acc*invn+bias) * norm   (pad rows -> 0)
template <int EPI, int SWS>
__global__ __launch_bounds__(256) void k_gemm_f16(const __half* __restrict__ S0,
                                                  const __half* __restrict__ S1,
                                                  const __half* __restrict__ S2,
                                                  const __half* __restrict__ Bh,
                                                  const float* __restrict__ bias,
                                                  const int* __restrict__ gidp, int Kdim,
                                                  __half* __restrict__ xOut) {
    const int SW = 1 << SWS;
    const int tid  = threadIdx.x;
    const int lane = tid & 31, warp = tid >> 5;
    const int gid  = lane >> 2, qid = lane & 3;
    const int wm   = (warp & 1) * 64;
    const int wn   = (warp >> 1) * 32;
    const long mbase = (long)blockIdx.y * BM;
    const int  nbase = blockIdx.x * BN;

    float acc[4][4][4];
#pragma unroll
    for (int mi = 0; mi < 4; mi++)
#pragma unroll
        for (int ni = 0; ni < 4; ni++)
#pragma unroll
            for (int r = 0; r < 4; r++) acc[mi][ni][r] = 0.f;

    const uint32_t smemB = (uint32_t)__cvta_generic_to_shared(smem_gemm);
    const int ntiles = Kdim / BKH;

    auto load_stage = [&](int t, int buf) {
        uint32_t sb = smemB + buf * STAGE_BYTES;
#pragma unroll
        for (int i = 0; i < 4; i++) {
            int ch = tid + 256 * i;
            int r = ch >> 3, kc = ch & 7;
            uint32_t dstA = sb + r * 128 + ((kc * 16) ^ ((r & 7) * 16));
            int kh = t * BKH + kc * 8;
            int sl = kh >> SWS;
            int off = kh & (SW - 1);
            const __half* base = (sl == 0) ? S0 : ((sl == 1) ? S1 : S2);
            cp16(dstA, base + (size_t)(mbase + r) * SW + off);
        }
#pragma unroll
        for (int i = 0; i < 4; i++) {
            int ch = tid + 256 * i;
            int r = ch >> 4, nc = ch & 15;
            uint32_t dstB = sb + A_BYTES + r * 256 + ((nc * 16) ^ ((r & 7) * 16));
            cp16(dstB, Bh + (size_t)(t * BKH + r) * 256 + nbase + nc * 8);
        }
        cp_commit();
    };

    const int Lr = lane & 7, sub = lane >> 3;
    const int rowLocal = Lr + (sub & 1) * 8;
    const int ksub16 = (sub >> 1) * 16;
    const uint32_t xorA = Lr * 16;
    const int bl = lane & 15;
    const uint32_t xorB = (lane & 7) * 16;

    load_stage(0, 0);
    load_stage(1, 1);
    for (int t = 0; t < ntiles; t++) {
        if (t + 2 < ntiles) { load_stage(t + 2, (t + 2) % NSTAGE); cp_wait<2>(); }
        else if (t + 1 < ntiles) cp_wait<1>();
        else cp_wait<0>();
        __syncthreads();
        uint32_t As = smemB + (t % NSTAGE) * STAGE_BYTES;
        uint32_t Bs = As + A_BYTES;
        uint32_t aRow[4];
#pragma unroll
        for (int mi = 0; mi < 4; mi++)
            aRow[mi] = As + (wm + mi * 16 + rowLocal) * 128;
        uint32_t bBase = Bs + bl * 256;
        uint32_t bOff[4];
#pragma unroll
        for (int ni = 0; ni < 4; ni++)
            bOff[ni] = (uint32_t)((wn + ni * 8) * 2) ^ xorB;
#pragma unroll
        for (int ks = 0; ks < 4; ks++) {
            uint32_t a[4][4], b[4][2];
#pragma unroll
            for (int mi = 0; mi < 4; mi++)
                ldsm4(a[mi], aRow[mi] + (uint32_t)((ks * 32 + ksub16) ^ xorA));
#pragma unroll
            for (int ni = 0; ni < 4; ni++)
                ldsm2t(b[ni], bBase + ks * 4096 + bOff[ni]);
#pragma unroll
            for (int mi = 0; mi < 4; mi++)
#pragma unroll
                for (int ni = 0; ni < 4; ni++)
                    mma_f16(acc[mi][ni], a[mi], b[ni]);
        }
        __syncthreads();
    }

    if (EPI == 1) {
#pragma unroll
        for (int mi = 0; mi < 4; mi++) {
            long r0 = mbase + wm + mi * 16 + gid;
            long r1 = r0 + 8;
            float i0 = (r0 < NV) ? __ldg(&d_invn[r0]) : 0.f;
            float i1 = (r1 < NV) ? __ldg(&d_invn[r1]) : 0.f;
            float n0 = (r0 < NV) ? __ldg(&d_norm[r0]) : 0.f;
            float n1 = (r1 < NV) ? __ldg(&d_norm[r1]) : 0.f;
#pragma unroll
            for (int ni = 0; ni < 4; ni++) {
                int col = nbase + wn + ni * 8 + 2 * qid;
                float b0 = bias[col], b1v = bias[col + 1];
                float v00 = fmaxf(fmaf(acc[mi][ni][0], i0, b0), 0.f);
                float v01 = fmaxf(fmaf(acc[mi][ni][1], i0, b1v), 0.f);
                float v10 = fmaxf(fmaf(acc[mi][ni][2], i1, b0), 0.f);
                float v11 = fmaxf(fmaf(acc[mi][ni][3], i1, b1v), 0.f);
                *(__half2*)&xOut[r0 * 256 + col] = __floats2half2_rn(v00 * n0, v01 * n0);
                *(__half2*)&xOut[r1 * 256 + col] = __floats2half2_rn(v10 * n1, v11 * n1);
            }
        }
    } else {
        // ---- fused segment-max pooling (all 256 threads: 2 row-halves per column) ----
        float* pool = (float*)smem_gemm;                         // [128][POOL_STRIDE]
        int* gsh = (int*)(smem_gemm + 128 * POOL_STRIDE * 4);    // [128]
#pragma unroll
        for (int mi = 0; mi < 4; mi++) {
            int rr0 = wm + mi * 16 + gid;
            int rr1 = rr0 + 8;
            long r0 = mbase + rr0, r1 = mbase + rr1;
            float i0 = (r0 < NV) ? __ldg(&d_invn[r0]) : 0.f;
            float i1 = (r1 < NV) ? __ldg(&d_invn[r1]) : 0.f;
#pragma unroll
            for (int ni = 0; ni < 4; ni++) {
                int c = wn + ni * 8 + 2 * qid;
                float b0 = bias[nbase + c], b1v = bias[nbase + c + 1];
                pool[rr0 * POOL_STRIDE + c]     = fmaxf(fmaf(acc[mi][ni][0], i0, b0), 0.f);
                pool[rr0 * POOL_STRIDE + c + 1] = fmaxf(fmaf(acc[mi][ni][1], i0, b1v), 0.f);
                pool[rr1 * POOL_STRIDE + c]     = fmaxf(fmaf(acc[mi][ni][2], i1, b0), 0.f);
                pool[rr1 * POOL_STRIDE + c + 1] = fmaxf(fmaf(acc[mi][ni][3], i1, b1v), 0.f);
            }
        }
        if (tid < 128) {
            long r = mbase + tid;
            gsh[tid] = (r < NV) ? __ldg(&gidp[r]) : -1;
        }
        __syncthreads();
        {
            int col  = tid & 127;
            int rlo  = (tid >> 7) * 64;        // 0 or 64
            int rhi  = rlo + 64;
            int g = gsh[rlo];
            float m = 0.f;
            for (int r = rlo; r < rhi; r++) {
                int g2 = gsh[r];
                if (g2 < 0) break;
                if (g2 != g) {
                    atomicMax((int*)&d_pooled[g * HIDN + nbase + col], __float_as_int(m));
                    m = 0.f;
                    g = g2;
                }
                m = fmaxf(m, pool[r * POOL_STRIDE + col]);
            }
            if (g >= 0)
                atomicMax((int*)&d_pooled[g * HIDN + nbase + col], __float_as_int(m));
        }
    }
}

// head + fused pooled tail-zero: 2 blocks x 320 threads, block b owns graphs
// [b*32, b*32+32) exclusively (reads AND zeroes only its own rows -> no race).
__global__ __launch_bounds__(320) void k_head(const float* __restrict__ Wc,
                                              const float* __restrict__ bc,
                                              float* __restrict__ out) {
    int b = blockIdx.x, t = threadIdx.x;
    int g = b * 32 + t / 10, c = t % 10;
    if (t < 320) {
        float s = bc[c];
#pragma unroll 8
        for (int hh = 0; hh < HIDN; hh++)
            s = fmaf(d_pooled[g * HIDN + hh], Wc[hh * 10 + c], s);
        out[g * 10 + c] = s;
    }
    __syncthreads();
    // zero this block's 32 pooled rows (32*256 floats = 2048 float4)
    float4* pz = (float4*)&d_pooled[b * 32 * HIDN];
    for (int i = t; i < 32 * HIDN / 4; i += 320)
        pz[i] = make_float4(0.f, 0.f, 0.f, 0.f);
}

// ---------------- launch ----------------
extern "C" void kernel_launch(void* const* d_in, const int* in_sizes, int n_in,
                              void* d_out, int out_size) {
    const float* h   = (const float*)d_in[0];
    const int*   src = (const int*)d_in[1];
    const int*   dst = (const int*)d_in[2];
    const int*   gid = (const int*)d_in[3];
    const float* W1  = (const float*)d_in[4];
    const float* b1  = (const float*)d_in[5];
    const float* W2  = (const float*)d_in[6];
    const float* b2  = (const float*)d_in[7];
    const float* Wc  = (const float*)d_in[8];
    const float* bc  = (const float*)d_in[9];
    float* out = (float*)d_out;
    const int E = in_sizes[1];

    __half *h16_, *hop1_, *hop2_, *x1h_, *g1_, *g2_, *w1h_, *w2h_;
    int *cnt_;
    cudaGetSymbolAddress((void**)&h16_,  d_h16);
    cudaGetSymbolAddress((void**)&hop1_, d_hop1);
    cudaGetSymbolAddress((void**)&hop2_, d_hop2);
    cudaGetSymbolAddress((void**)&x1h_,  d_x1h);
    cudaGetSymbolAddress((void**)&g1_,   d_g1);
    cudaGetSymbolAddress((void**)&g2_,   d_g2);
    cudaGetSymbolAddress((void**)&w1h_,  d_w1h);
    cudaGetSymbolAddress((void**)&w2h_,  d_w2h);
    cudaGetSymbolAddress((void**)&cnt_,  d_cnt);

    cudaFuncSetAttribute((const void*)k_gemm_f16<1, 7>,
                         cudaFuncAttributeMaxDynamicSharedMemorySize, GEMM_SMEM_BYTES);
    cudaFuncSetAttribute((const void*)k_gemm_f16<0, 8>,
                         cudaFuncAttributeMaxDynamicSharedMemorySize, GEMM_SMEM_BYTES);

    static cudaStream_t s1 = nullptr;
    static cudaEvent_t evFork = nullptr, evNorm = nullptr, evJoin = nullptr;
    if (!s1) {
        cudaStreamCreateWithFlags(&s1, cudaStreamNonBlocking);
        cudaEventCreateWithFlags(&evFork, cudaEventDisableTiming);
        cudaEventCreateWithFlags(&evNorm, cudaEventDisableTiming);
        cudaEventCreateWithFlags(&evJoin, cudaEventDisableTiming);
    }

    // ---- fork: weights on s1 (independent); degree chain on main ----
    // Invariant: d_cnt and d_pooled are ZERO at launch entry (.bss on first call;
    // tail-zeroed inside every launch thereafter -> holds for each graph replay).
    cudaEventRecord(evFork, 0);
    cudaStreamWaitEvent(s1, evFork, 0);
    k_roundh<<<(384 * 128 + 255) / 256, 256, 0, s1>>>(w1h_, W1, 384 * 128);
    k_roundh<<<(768 * 128 + 255) / 256, 256, 0, s1>>>(w2h_, W2, 768 * 128);

    k_degi<<<(E + 255) / 256, 256>>>(dst, E);
    const int NB = (NV + 1023) / 1024;
    k_scan_local<<<NB, 256>>>();
    k_scan_blk<<<1, 128>>>(NB);
    k_addoff<<<(NV + 255) / 256, 256>>>(E);
    cudaEventRecord(evNorm, 0);

    // csrbuild (atomic-free) on main; prep0 + cnt tail-zero on s1
    cudaStreamWaitEvent(s1, evNorm, 0);
    k_prep0<<<(unsigned)(((long)NV * 16 + 255) / 256), 256, 0, s1>>>((const float4*)h,
                                                                     (uint4*)h16_);
    k_zero<<<(NV / 4 + 255) / 256, 256, 0, s1>>>((float4*)cnt_, NV / 4);
    cudaEventRecord(evJoin, s1);
    k_csrbuild<<<(E + 255) / 256, 256>>>(src, dst, E);
    cudaStreamWaitEvent(0, evJoin, 0);

    // ---- layer 1 (d=128) ----
    k_agg<128, false><<<(NV + 15) / 16, 256>>>(h16_, hop1_);
    k_agg<128, true ><<<(NV + 15) / 16, 256>>>(hop1_, hop2_);   // final hop: stream
    k_gemm_f16<1, 7><<<dim3(2, MPAD / 128), 256, GEMM_SMEM_BYTES>>>(
        h16_, hop1_, hop2_, w1h_, b1, nullptr, 384, x1h_);

    // ---- layer 2 (d=256) ----
    k_agg<256, false><<<(NV + 7) / 8, 256>>>(x1h_, g1_);
    k_agg<256, true ><<<(NV + 7) / 8, 256>>>(g1_, g2_);         // final hop: stream
    k_gemm_f16<0, 8><<<dim3(2, MPAD / 128), 256, GEMM_SMEM_BYTES>>>(
        x1h_, g1_, g2_, w2h_, b2, gid, 768, nullptr);

    // ---- head (fused pooled tail-zero) ----
    k_head<<<2, 320>>>(Wc, bc, out);
}